// round 2
// baseline (speedup 1.0000x reference)
#include <cuda_runtime.h>
#include <math.h>

// ---------------------------------------------------------------------------
// Problem constants (fixed by the dataset): N=10000, E=160000, D=32, H=16,
// NB=16, NUM_ATOMS=100, CUT=6, DEG=4, OUT=1.
// ---------------------------------------------------------------------------
#define MAXN 10240

// Scratch (static device globals — no runtime allocation)
__device__ float  z0g[MAXN * 16];    // per-node scalar features (already /DEG)
__device__ float  z1g[MAXN * 48];    // per-node vector features (already /DEG)
__device__ float  TAg[100 * 256];    // TA[a][j][h] = sum_d emb[a][d]*fc0_w2[j][d*16+h]
__device__ float  TBg[100 * 256];    // TB: same with +512 column offset
__device__ double Gg[512];           // G[h'*16 + j] = sum_e h2[e][j] * ut[e][h']

// Math constants
#define PI_D    3.141592653589793
#define TWO_PI  6.283185307179586
#define INV_2PI 0.15915494309189535
#define BSCALE  2.3094010767585034       // sqrt(2/6)*sqrt(16)
#define SQ3I4P  0.4886025119029199       // sqrt(3)/sqrt(4*pi)
#define Y0C     0.28209479177387814f     // 1/sqrt(4*pi)
#define RSQRT3  0.5773502691896258f      // 1/sqrt(3)
#define C0      0.0031167365657f         // Y0 * (1/sqrt(32)) / 16   (fc /4, n0, /DEG)
#define CBC     0.011048543456039805f    // (1/sqrt(32)) / 16
#define N1D16   0.011048543456039805     // n1/16 = (1/sqrt(32))/16  (double)

// ---------------------------------------------------------------------------
// Kernel 0: zero scratch + build per-atom-type tables TA/TB
// ---------------------------------------------------------------------------
__global__ __launch_bounds__(256) void init_kernel(
    const float* __restrict__ atom_emb, const float* __restrict__ fc0_w2,
    int N, int NA)
{
    int b = blockIdx.x;
    int t = threadIdx.x;
    if (b < NA) {
        int j = t >> 4, h = t & 15;
        float ta = 0.0f, tb = 0.0f;
        #pragma unroll
        for (int d = 0; d < 32; d++) {
            float x = atom_emb[b * 32 + d];
            ta += x * fc0_w2[j * 1024 + d * 16 + h];
            tb += x * fc0_w2[j * 1024 + 512 + d * 16 + h];
        }
        TAg[b * 256 + t] = ta;
        TBg[b * 256 + t] = tb;
    } else {
        if (b == NA) { Gg[t] = 0.0; Gg[t + 256] = 0.0; }
        int tot = N * 64;
        int idx = (b - NA) * 256 + t;
        int stride = (gridDim.x - NA) * 256;
        for (int i = idx; i < tot; i += stride) {
            if (i < N * 16) z0g[i] = 0.0f;
            else            z1g[i - N * 16] = 0.0f;
        }
    }
}

// Accurate bessel-phase sine: arg = (k+1)*pi*dist/6 computed & range-reduced
// in double, evaluated with sinf on the small reduced argument.
__device__ __forceinline__ float bessel_sin(double ck, double dist) {
    double arg = ck * dist;
    double q = rint(arg * INV_2PI);
    float r = (float)(arg - q * TWO_PI);
    return sinf(r);
}

// ---------------------------------------------------------------------------
// Kernel 1: phase-1 message passing. 16 threads per edge (thread k owns h=k).
// ---------------------------------------------------------------------------
__global__ __launch_bounds__(256) void phase1_kernel(
    const int* __restrict__ an, const float* __restrict__ coords,
    const int* __restrict__ ei, const float* __restrict__ fc0_w1, int E)
{
    __shared__ float sw1[256];
    __shared__ float sb[16][17];
    __shared__ float sh1[16][17];
    int t = threadIdx.x;
    sw1[t] = fc0_w1[t];
    __syncthreads();
    int g = t >> 4, k = t & 15;
    double ck = (double)(k + 1) * PI_D / 6.0;

    for (int base = blockIdx.x * 16; base < E; base += gridDim.x * 16) {
        int e = base + g;
        bool act = e < E;
        int e0 = act ? e : 0;
        int src = ei[e0];
        int dst = ei[E + e0];
        double dx = (double)coords[src * 3 + 0] - (double)coords[dst * 3 + 0];
        double dy = (double)coords[src * 3 + 1] - (double)coords[dst * 3 + 1];
        double dz = (double)coords[src * 3 + 2] - (double)coords[dst * 3 + 2];
        double dist = sqrt(dx * dx + dy * dy + dz * dz);
        double inv = 1.0 / fmax(dist, 1e-9);
        float y1x = (float)(SQ3I4P * dx * inv);
        float y1y = (float)(SQ3I4P * dy * inv);
        float y1z = (float)(SQ3I4P * dz * inv);
        float bsf = (dist < 6.0) ? (float)(BSCALE * inv) : 0.0f;
        sb[g][k] = bsf * bessel_sin(ck, dist);
        __syncwarp();
        float acc = 0.0f;
        #pragma unroll
        for (int i = 0; i < 16; i++) acc += sb[g][i] * sw1[i * 16 + k];
        acc *= 0.25f;
        float h1k = acc / (1.0f + expf(-acc));
        sh1[g][k] = h1k;
        __syncwarp();
        int a = an[src];
        const float* ta = TAg + a * 256 + k;
        const float* tb = TBg + a * 256 + k;
        float m0 = 0.0f, mb = 0.0f;
        #pragma unroll
        for (int j = 0; j < 16; j++) {
            float hj = sh1[g][j];
            m0 += hj * ta[j * 16];
            mb += hj * tb[j * 16];
        }
        if (act) {
            atomicAdd(&z0g[dst * 16 + k], m0 * C0);
            float w = mb * CBC;
            atomicAdd(&z1g[dst * 48 + k * 3 + 0], w * y1x);
            atomicAdd(&z1g[dst * 48 + k * 3 + 1], w * y1y);
            atomicAdd(&z1g[dst * 48 + k * 3 + 2], w * y1z);
        }
        __syncwarp();
    }
}

// ---------------------------------------------------------------------------
// Kernel 2: phase-2 sum-exchange:
//   G[h'][j] = sum_e h2[e][j] * ut[e][h'],
//   ut[h] = y0*z0[src][h],  ut[16+h] = (z1[src][h]·y1)/sqrt(3)
// Per-thread fp32 partials (~20 edges), block+global reduce in double.
// ---------------------------------------------------------------------------
__global__ __launch_bounds__(256) void phase2_kernel(
    const float* __restrict__ coords, const int* __restrict__ ei,
    const float* __restrict__ fc1_w1, int E)
{
    __shared__ float sw1[256];
    __shared__ float sb[16][17];
    __shared__ float sut[16 * 33];
    __shared__ double Gs[512];
    int t = threadIdx.x;
    sw1[t] = fc1_w1[t];
    Gs[t] = 0.0;
    Gs[t + 256] = 0.0;
    __syncthreads();
    int g = t >> 4, k = t & 15;
    double ck = (double)(k + 1) * PI_D / 6.0;

    float Gk[32];
    #pragma unroll
    for (int h = 0; h < 32; h++) Gk[h] = 0.0f;

    for (int base = blockIdx.x * 16; base < E; base += gridDim.x * 16) {
        int e = base + g;
        bool act = e < E;
        int e0 = act ? e : 0;
        int src = ei[e0];
        int dst = ei[E + e0];
        double dx = (double)coords[src * 3 + 0] - (double)coords[dst * 3 + 0];
        double dy = (double)coords[src * 3 + 1] - (double)coords[dst * 3 + 1];
        double dz = (double)coords[src * 3 + 2] - (double)coords[dst * 3 + 2];
        double dist = sqrt(dx * dx + dy * dy + dz * dz);
        double inv = 1.0 / fmax(dist, 1e-9);
        float y1x = (float)(SQ3I4P * dx * inv);
        float y1y = (float)(SQ3I4P * dy * inv);
        float y1z = (float)(SQ3I4P * dz * inv);
        float bsf = (dist < 6.0) ? (float)(BSCALE * inv) : 0.0f;
        sb[g][k] = bsf * bessel_sin(ck, dist);
        __syncwarp();
        float acc = 0.0f;
        #pragma unroll
        for (int i = 0; i < 16; i++) acc += sb[g][i] * sw1[i * 16 + k];
        acc *= 0.25f;
        float h2k = acc / (1.0f + expf(-acc));
        if (!act) h2k = 0.0f;
        float sk = z0g[src * 16 + k];
        float v0 = z1g[src * 48 + k * 3 + 0];
        float v1 = z1g[src * 48 + k * 3 + 1];
        float v2 = z1g[src * 48 + k * 3 + 2];
        sut[g * 33 + k] = Y0C * sk;
        sut[g * 33 + 16 + k] = (v0 * y1x + v1 * y1y + v2 * y1z) * RSQRT3;
        __syncwarp();
        #pragma unroll
        for (int h = 0; h < 32; h++) Gk[h] += h2k * sut[g * 33 + h];
        __syncwarp();
    }

    __syncthreads();
    #pragma unroll
    for (int h = 0; h < 32; h++) atomicAdd(&Gs[h * 16 + k], (double)Gk[h]);
    __syncthreads();
    atomicAdd(&Gg[t], Gs[t]);
    atomicAdd(&Gg[t + 256], Gs[t + 256]);
}

// ---------------------------------------------------------------------------
// Kernel 3: final (all double).
//   out = sum_k( (n1/16)*OC[k] + S0[k] ) * r[k] * 0.25
// ---------------------------------------------------------------------------
__global__ __launch_bounds__(256) void final_kernel(
    const float* __restrict__ fc1_w2, const float* __restrict__ w_readout,
    float* __restrict__ out, int N)
{
    __shared__ double sred[256];
    __shared__ double S0[16];
    int t = threadIdx.x;
    int comp = t & 15;
    double part = 0.0;
    for (int n = t >> 4; n < N; n += 16) part += (double)z0g[n * 16 + comp];
    sred[t] = part;
    __syncthreads();
    if (t < 16) {
        double s = 0.0;
        for (int w = 0; w < 16; w++) s += sred[w * 16 + t];
        S0[t] = s;
    }
    __syncthreads();
    double term = 0.0;
    if (t < 16) {
        double oc = 0.0;
        for (int j = 0; j < 16; j++) {
            #pragma unroll
            for (int hp = 0; hp < 32; hp++) {
                int col = (hp < 16) ? (hp * 16 + t) : (768 + (hp - 16) * 16 + t);
                oc += Gg[hp * 16 + j] * (double)fc1_w2[j * 1024 + col];
            }
        }
        term = (oc * N1D16 + S0[t]) * (double)w_readout[t] * 0.25;
    }
    __syncthreads();
    sred[t] = term;
    __syncthreads();
    if (t == 0) {
        double s = 0.0;
        for (int i = 0; i < 16; i++) s += sred[i];
        out[0] = (float)s;
    }
}

// ---------------------------------------------------------------------------
// Launch
// ---------------------------------------------------------------------------
extern "C" void kernel_launch(void* const* d_in, const int* in_sizes, int n_in,
                              void* d_out, int out_size)
{
    const int*   an        = (const int*)  d_in[0];
    const float* coords    = (const float*)d_in[1];
    const int*   ei        = (const int*)  d_in[2];
    const float* atom_emb  = (const float*)d_in[3];
    const float* fc0_w1    = (const float*)d_in[4];
    const float* fc0_w2    = (const float*)d_in[5];
    const float* fc1_w1    = (const float*)d_in[6];
    const float* fc1_w2    = (const float*)d_in[7];
    const float* w_readout = (const float*)d_in[8];
    float* out = (float*)d_out;

    int N  = in_sizes[0];
    int E  = in_sizes[2] / 2;
    int NA = in_sizes[3] / 32;   // 100 atom types

    init_kernel<<<NA + 256, 256>>>(atom_emb, fc0_w2, N, NA);
    phase1_kernel<<<512, 256>>>(an, coords, ei, fc0_w1, E);
    phase2_kernel<<<512, 256>>>(coords, ei, fc1_w1, E);
    final_kernel<<<1, 256>>>(fc1_w2, w_readout, out, N);
}

// round 3
// speedup vs baseline: 6.3836x; 6.3836x over previous
#include <cuda_runtime.h>
#include <math.h>

// ---------------------------------------------------------------------------
// Problem constants: N=10000, E=160000, D=32, H=16, NB=16, NUM_ATOMS=100,
// CUT=6, DEG=4, OUT=1.
// ---------------------------------------------------------------------------
#define MAXN 10240
#define EMAX 163840

// Scratch (static device globals)
// zg[n][k] = {z0[k], z1[k][0], z1[k][1], z1[k][2]}  (already /DEG folded)
__device__ float4  zg[MAXN * 16];
__device__ float2  TABg[100 * 256];   // [a][j*16+h] = {TA, TB}
__device__ float   basisg[EMAX * 16]; // per-edge bessel basis (phase1 -> phase2)
__device__ float   y1g[EMAX * 3];     // per-edge unit-vector sph harm l=1
__device__ double  Gg[512];           // G[h'*16 + j]
__device__ double  S0g[16];           // sum_n z0[n][k]

// Math constants
#define PI_D    3.141592653589793
#define TWO_PI  6.283185307179586
#define INV_2PI 0.15915494309189535
#define BSCALE  2.3094010767585034       // sqrt(2/6)*sqrt(16)
#define SQ3I4P  0.4886025119029199       // sqrt(3)/sqrt(4*pi)
#define Y0C     0.28209479177387814f     // 1/sqrt(4*pi)
#define RSQRT3  0.5773502691896258f      // 1/sqrt(3)
#define C0      0.0031167365657f         // Y0 * (1/sqrt(32)) / 16
#define CBC     0.011048543456039805f    // (1/sqrt(32)) / 16
#define N1D16   0.011048543456039805     // n1/16 (double)

// f32x2 helpers -------------------------------------------------------------
__device__ __forceinline__ unsigned long long pack2(float lo, float hi) {
    float2 f = make_float2(lo, hi);
    unsigned long long r;
    memcpy(&r, &f, 8);
    return r;
}
__device__ __forceinline__ void fma2(unsigned long long& acc,
                                     unsigned long long a, unsigned long long b) {
    asm("fma.rn.f32x2 %0, %1, %2, %3;" : "=l"(acc) : "l"(a), "l"(b), "l"(acc));
}
__device__ __forceinline__ unsigned long long add2(unsigned long long a,
                                                   unsigned long long b) {
    unsigned long long r;
    asm("add.rn.f32x2 %0, %1, %2;" : "=l"(r) : "l"(a), "l"(b));
    return r;
}
__device__ __forceinline__ float2 unpack2(unsigned long long v) {
    float2 f;
    memcpy(&f, &v, 8);
    return f;
}

// Accurate bessel-phase sine: double range reduction, fp32 sin on small arg.
__device__ __forceinline__ float bessel_sin(double ck, double dist) {
    double arg = ck * dist;
    double q = rint(arg * INV_2PI);
    float r = (float)(arg - q * TWO_PI);
    return sinf(r);
}

// ---------------------------------------------------------------------------
// Kernel 0: build TABg (interleaved TA/TB) + zero zg/Gg/S0g
// ---------------------------------------------------------------------------
__global__ __launch_bounds__(256) void init_kernel(
    const float* __restrict__ atom_emb, const float* __restrict__ fc0_w2,
    int N, int NA)
{
    int b = blockIdx.x;
    int t = threadIdx.x;
    if (b < NA) {
        int j = t >> 4, h = t & 15;
        float ta = 0.0f, tb = 0.0f;
        #pragma unroll
        for (int d = 0; d < 32; d++) {
            float x = atom_emb[b * 32 + d];
            ta += x * fc0_w2[j * 1024 + d * 16 + h];
            tb += x * fc0_w2[j * 1024 + 512 + d * 16 + h];
        }
        TABg[b * 256 + t] = make_float2(ta, tb);
    } else {
        if (b == NA && t < 16) S0g[t] = 0.0;
        if (b == NA + 1) { Gg[t] = 0.0; Gg[t + 256] = 0.0; }
        int tot = N * 16;  // float4 count
        int idx = (b - NA) * 256 + t;
        int stride = (gridDim.x - NA) * 256;
        for (int i = idx; i < tot; i += stride)
            zg[i] = make_float4(0.f, 0.f, 0.f, 0.f);
    }
}

// ---------------------------------------------------------------------------
// Kernel 1: phase-1. Stage 256 edges' geometry (thread-per-edge), then
// 16-thread groups consume 16 edges each. One red.v4 atomic per (edge,k).
// ---------------------------------------------------------------------------
__global__ __launch_bounds__(256) void phase1_kernel(
    const int* __restrict__ an, const float* __restrict__ coords,
    const int* __restrict__ ei, const float* __restrict__ fc0_w1, int E)
{
    __shared__ double sdist[256];
    __shared__ float sbsf[256], sy1x[256], sy1y[256], sy1z[256];
    __shared__ int sa[256], sdst[256];
    __shared__ float sb[16][17];
    __shared__ float sh1[16][17];
    __shared__ float sS0[16];

    int t = threadIdx.x, g = t >> 4, k = t & 15;
    double ck = (double)(k + 1) * PI_D / 6.0;

    float rw1[16];
    #pragma unroll
    for (int i = 0; i < 16; i++) rw1[i] = fc0_w1[i * 16 + k];
    if (t < 16) sS0[t] = 0.0f;
    float s0acc = 0.0f;

    for (int base = blockIdx.x * 256; base < E; base += gridDim.x * 256) {
        int e = base + t;
        if (e < E) {
            int src = ei[e], dst = ei[E + e];
            double dx = (double)coords[src * 3 + 0] - (double)coords[dst * 3 + 0];
            double dy = (double)coords[src * 3 + 1] - (double)coords[dst * 3 + 1];
            double dz = (double)coords[src * 3 + 2] - (double)coords[dst * 3 + 2];
            double dist = sqrt(dx * dx + dy * dy + dz * dz);
            double inv = 1.0 / fmax(dist, 1e-9);
            sdist[t] = dist;
            sbsf[t] = (dist < 6.0) ? (float)(BSCALE * inv) : 0.0f;
            float yx = (float)(SQ3I4P * dx * inv);
            float yy = (float)(SQ3I4P * dy * inv);
            float yz = (float)(SQ3I4P * dz * inv);
            sy1x[t] = yx; sy1y[t] = yy; sy1z[t] = yz;
            y1g[(size_t)e * 3 + 0] = yx;
            y1g[(size_t)e * 3 + 1] = yy;
            y1g[(size_t)e * 3 + 2] = yz;
            sa[t] = an[src];
            sdst[t] = dst;
        }
        __syncthreads();
        int nloc = E - base; if (nloc > 256) nloc = 256;

        #pragma unroll 1
        for (int i = 0; i < 16; i++) {
            int le = g * 16 + i;
            bool eact = le < nloc;
            float bsv = sbsf[le] * bessel_sin(ck, sdist[le]);
            sb[g][k] = bsv;
            if (eact) basisg[(size_t)(base + le) * 16 + k] = bsv;
            __syncwarp();
            float acc = 0.0f;
            #pragma unroll
            for (int j = 0; j < 16; j++) acc += sb[g][j] * rw1[j];
            acc *= 0.25f;
            float h1 = acc / (1.0f + expf(-acc));
            sh1[g][k] = h1;
            __syncwarp();
            int a = sa[le];
            const unsigned long long* tab =
                (const unsigned long long*)(TABg + a * 256 + k);
            unsigned long long mm = pack2(0.0f, 0.0f);
            #pragma unroll
            for (int j = 0; j < 16; j++) {
                unsigned long long hj2 = pack2(sh1[g][j], sh1[g][j]);
                fma2(mm, tab[j * 16], hj2);
            }
            if (eact) {
                float2 m = unpack2(mm);
                float m0c = m.x * C0;
                float w = m.y * CBC;
                s0acc += m0c;
                float vy = w * sy1x[le], vz = w * sy1y[le], vw = w * sy1z[le];
                float* dp = (float*)&zg[(size_t)sdst[le] * 16 + k];
                asm volatile(
                    "red.global.add.v4.f32 [%0], {%1, %2, %3, %4};"
                    :: "l"(__cvta_generic_to_global(dp)),
                       "f"(m0c), "f"(vy), "f"(vz), "f"(vw)
                    : "memory");
            }
            __syncwarp();
        }
        __syncthreads();
    }

    atomicAdd(&sS0[k], s0acc);
    __syncthreads();
    if (t < 16) atomicAdd(&S0g[t], (double)sS0[t]);
}

// ---------------------------------------------------------------------------
// Kernel 2: phase-2 sum-exchange. Reads cached basis/y1, gathers zg[src],
// accumulates G[h'][j] in packed f32x2 registers, reduces via shfl + smem,
// commits per-block partials with double global atomics.
// ---------------------------------------------------------------------------
__global__ __launch_bounds__(256) void phase2_kernel(
    const int* __restrict__ ei, const float* __restrict__ fc1_w1, int E)
{
    __shared__ double sutd[16 * 17];          // 34 floats per group, 8B aligned
    __shared__ float sb[16][17];
    __shared__ unsigned long long swG[8 * 16 * 16];  // 16KB
    float* sut = (float*)sutd;

    int t = threadIdx.x, g = t >> 4, k = t & 15;

    float rw1[16];
    #pragma unroll
    for (int i = 0; i < 16; i++) rw1[i] = fc1_w1[i * 16 + k];

    unsigned long long Gk[16];
    #pragma unroll
    for (int hi = 0; hi < 16; hi++) Gk[hi] = pack2(0.0f, 0.0f);

    for (int base = blockIdx.x * 256; base < E; base += gridDim.x * 256) {
        int nloc = E - base; if (nloc > 256) nloc = 256;
        #pragma unroll 1
        for (int i = 0; i < 16; i++) {
            int le = g * 16 + i;
            bool eact = le < nloc;
            int e0 = eact ? (base + le) : base;
            sb[g][k] = basisg[(size_t)e0 * 16 + k];
            int src = ei[e0];
            float y1x = y1g[(size_t)e0 * 3 + 0];
            float y1y = y1g[(size_t)e0 * 3 + 1];
            float y1z = y1g[(size_t)e0 * 3 + 2];
            __syncwarp();
            float acc = 0.0f;
            #pragma unroll
            for (int j = 0; j < 16; j++) acc += sb[g][j] * rw1[j];
            acc *= 0.25f;
            float h2 = acc / (1.0f + expf(-acc));
            if (!eact) h2 = 0.0f;
            float4 zv = zg[(size_t)src * 16 + k];
            sut[g * 34 + k] = Y0C * zv.x;
            sut[g * 34 + 16 + k] = (zv.y * y1x + zv.z * y1y + zv.w * y1z) * RSQRT3;
            __syncwarp();
            unsigned long long h22 = pack2(h2, h2);
            const unsigned long long* srow =
                (const unsigned long long*)(sut + g * 34);
            #pragma unroll
            for (int hi = 0; hi < 16; hi++) fma2(Gk[hi], srow[hi], h22);
            __syncwarp();
        }
    }

    // in-warp reduce across the two half-warp groups
    #pragma unroll
    for (int hi = 0; hi < 16; hi++) {
        unsigned long long o = __shfl_down_sync(0xffffffffu, Gk[hi], 16);
        Gk[hi] = add2(Gk[hi], o);
    }
    int w = t >> 5;
    if ((t & 16) == 0) {
        #pragma unroll
        for (int hi = 0; hi < 16; hi++) swG[(w * 16 + k) * 16 + hi] = Gk[hi];
    }
    __syncthreads();
    // 256 threads: k2 = t&15 (j index), hi = t>>4 (h' pair)
    int k2 = t & 15, hi = t >> 4;
    double glo = 0.0, ghi = 0.0;
    #pragma unroll
    for (int w2 = 0; w2 < 8; w2++) {
        float2 f = unpack2(swG[(w2 * 16 + k2) * 16 + hi]);
        glo += (double)f.x;
        ghi += (double)f.y;
    }
    atomicAdd(&Gg[(2 * hi) * 16 + k2], glo);
    atomicAdd(&Gg[(2 * hi + 1) * 16 + k2], ghi);
}

// ---------------------------------------------------------------------------
// Kernel 3: final (tiny, all double).
// out = sum_k ( G-contraction[k]*n1/16 + S0[k] ) * w_readout[k] * 0.25
// ---------------------------------------------------------------------------
__global__ __launch_bounds__(256) void final_kernel(
    const float* __restrict__ fc1_w2, const float* __restrict__ w_readout,
    float* __restrict__ out)
{
    __shared__ double sred[256];
    __shared__ double sterm[16];
    int t = threadIdx.x;
    int k = t & 15, j = t >> 4;
    double oc = 0.0;
    #pragma unroll
    for (int hp = 0; hp < 32; hp++) {
        int col = (hp < 16) ? (hp * 16 + k) : (768 + (hp - 16) * 16 + k);
        oc += Gg[hp * 16 + j] * (double)fc1_w2[j * 1024 + col];
    }
    sred[t] = oc;
    __syncthreads();
    if (t < 16) {
        double s = 0.0;
        for (int j2 = 0; j2 < 16; j2++) s += sred[j2 * 16 + t];
        sterm[t] = (s * N1D16 + S0g[t]) * (double)w_readout[t] * 0.25;
    }
    __syncthreads();
    if (t == 0) {
        double s = 0.0;
        for (int i = 0; i < 16; i++) s += sterm[i];
        out[0] = (float)s;
    }
}

// ---------------------------------------------------------------------------
// Launch
// ---------------------------------------------------------------------------
extern "C" void kernel_launch(void* const* d_in, const int* in_sizes, int n_in,
                              void* d_out, int out_size)
{
    const int*   an        = (const int*)  d_in[0];
    const float* coords    = (const float*)d_in[1];
    const int*   ei        = (const int*)  d_in[2];
    const float* atom_emb  = (const float*)d_in[3];
    const float* fc0_w1    = (const float*)d_in[4];
    const float* fc0_w2    = (const float*)d_in[5];
    const float* fc1_w1    = (const float*)d_in[6];
    const float* fc1_w2    = (const float*)d_in[7];
    const float* w_readout = (const float*)d_in[8];
    float* out = (float*)d_out;

    int N  = in_sizes[0];
    int E  = in_sizes[2] / 2;
    int NA = in_sizes[3] / 32;   // 100 atom types

    int gp = (E + 255) / 256;    // 625 blocks: one sweep

    init_kernel<<<NA + 512, 256>>>(atom_emb, fc0_w2, N, NA);
    phase1_kernel<<<gp, 256>>>(an, coords, ei, fc0_w1, E);
    phase2_kernel<<<gp, 256>>>(ei, fc1_w1, E);
    final_kernel<<<1, 256>>>(fc1_w2, w_readout, out);
}